// round 16
// baseline (speedup 1.0000x reference)
#include <cuda_runtime.h>
#include <cuda_bf16.h>
#include <cuda_fp16.h>
#include <cstdint>

#define NNODES 50000
#define FDIM   256
#define HEADS1 4
#define MAXE   900000
#define MPAD   50048

// ---------------- device scratch ----------------
__device__ __align__(16) __half g_h16[(size_t)MPAD * FDIM];
__device__ __align__(16) float g_act[(size_t)NNODES * FDIM];   // reused as __half for layer-2 input
__device__ __align__(16) float g_als[(size_t)NNODES * HEADS1];
__device__ __align__(16) float g_ald[(size_t)NNODES * HEADS1];
__device__ __align__(16) int g_cnt[NNODES];
__device__ int   g_off[NNODES + 1];
__device__ int   g_cur[NNODES];
__device__ int   g_csr[MAXE];
__device__ int   g_part[64];
__device__ int   g_pbase[64];
__device__ __align__(16) __nv_bfloat16 g_b1hi[FDIM * FDIM];
__device__ __align__(16) __nv_bfloat16 g_b1lo[FDIM * FDIM];
__device__ __align__(16) __nv_bfloat16 g_b2hi[FDIM * FDIM];
__device__ __align__(16) __nv_bfloat16 g_b2lo[FDIM * FDIM];

// ---------------- HMMA + split helpers ----------------
__device__ __forceinline__ void mma16816(float* c, const uint4& a, const uint2& b) {
    asm volatile(
        "mma.sync.aligned.m16n8k16.row.col.f32.bf16.bf16.f32 "
        "{%0,%1,%2,%3}, {%4,%5,%6,%7}, {%8,%9}, {%0,%1,%2,%3};"
        : "+f"(c[0]), "+f"(c[1]), "+f"(c[2]), "+f"(c[3])
        : "r"(a.x), "r"(a.y), "r"(a.z), "r"(a.w), "r"(b.x), "r"(b.y));
}

__device__ __forceinline__ void split2(float2 v, uint32_t& hi, uint32_t& lo) {
    uint32_t ux = __float_as_uint(v.x), uy = __float_as_uint(v.y);
    hi = __byte_perm(ux, uy, 0x7632);
    float lx = v.x - __uint_as_float(ux & 0xFFFF0000u);
    float ly = v.y - __uint_as_float(uy & 0xFFFF0000u);
    asm("cvt.rn.bf16x2.f32 %0, %1, %2;" : "=r"(lo) : "f"(ly), "f"(lx));
}

// A-tile loaders: fp32 or fp16 input, both return float2
__device__ __forceinline__ float2 lda_t(const float* __restrict__ A, int row, int k, int n) {
    return (row < n) ? *(const float2*)(A + (size_t)row * 256 + k) : make_float2(0.f, 0.f);
}
__device__ __forceinline__ float2 lda_t(const __half* __restrict__ A, int row, int k, int n) {
    return (row < n) ? __half22float2(*(const __half2*)(A + (size_t)row * 256 + k))
                     : make_float2(0.f, 0.f);
}

// ---------------- W fragment conversion ----------------
__global__ void conv_wfrag_kernel(const float* __restrict__ W,
                                  uint32_t* __restrict__ hi, uint32_t* __restrict__ lo) {
    int u = blockIdx.x * blockDim.x + threadIdx.x;
    if (u >= FDIM * FDIM / 2) return;
    int r    = u & 1;
    int lane = (u >> 1) & 31;
    int blk  = u >> 6;
    int kstep = blk & 15;
    int ntile = blk >> 4;
    int g = lane >> 2, tig = lane & 3;
    int nn = ntile * 8 + g;
    int k  = kstep * 16 + r * 8 + tig * 2;
    float2 v = make_float2(W[(size_t)k * 256 + nn], W[(size_t)(k + 1) * 256 + nn]);
    uint32_t h, l;
    split2(v, h, l);
    hi[u] = h; lo[u] = l;
}

// ---------------- HMMA GEMM (64x128 block, 2m x 4n warps) + fused epilogue -------
template <int HEADS, typename AT>
__global__ void __launch_bounds__(256)
gemm_mma_kernel(const AT* __restrict__ A,
                const uint2* __restrict__ b_hi, const uint2* __restrict__ b_lo,
                __half* __restrict__ h16,
                const float* __restrict__ a_src, const float* __restrict__ a_dst,
                float* __restrict__ als, float* __restrict__ ald, int n) {
    constexpr int HID = 256 / HEADS;
    constexpr int HL  = (HEADS == 4) ? 2 : 1;
    int t = threadIdx.x, lane = t & 31, wid = t >> 5;
    int wm = wid & 1, wn = wid >> 1;
    int bx = blockIdx.x;
    int mt_base = blockIdx.y * 4 + wm * 2;
    int nt_base = bx * 16 + wn * 4;
    int g = lane >> 2, tig = lane & 3, tt = lane & 3;

    float acc[2][4][4];
    #pragma unroll
    for (int m = 0; m < 2; m++)
        #pragma unroll
        for (int j = 0; j < 4; j++)
            #pragma unroll
            for (int q = 0; q < 4; q++) acc[m][j][q] = 0.f;

    #pragma unroll 4
    for (int ks = 0; ks < 16; ks++) {
        int kk = ks * 16 + tig * 2;
        uint4 ah[2], al[2];
        #pragma unroll
        for (int m = 0; m < 2; m++) {
            int row0 = (mt_base + m) * 16 + g;
            float2 v00 = lda_t(A, row0,     kk,     n);
            float2 v10 = lda_t(A, row0 + 8, kk,     n);
            float2 v01 = lda_t(A, row0,     kk + 8, n);
            float2 v11 = lda_t(A, row0 + 8, kk + 8, n);
            split2(v00, ah[m].x, al[m].x);
            split2(v10, ah[m].y, al[m].y);
            split2(v01, ah[m].z, al[m].z);
            split2(v11, ah[m].w, al[m].w);
        }
        uint2 bh[4], bl[4];
        #pragma unroll
        for (int j = 0; j < 4; j++) {
            int idx = ((nt_base + j) * 16 + ks) * 32 + lane;
            bh[j] = b_hi[idx];
            bl[j] = b_lo[idx];
        }
        #pragma unroll
        for (int m = 0; m < 2; m++)
            #pragma unroll
            for (int j = 0; j < 4; j++) {
                mma16816(acc[m][j], ah[m], bh[j]);
                mma16816(acc[m][j], ah[m], bl[j]);
                mma16816(acc[m][j], al[m], bh[j]);
            }
    }

    // ---- store fp16 features ----
    #pragma unroll
    for (int m = 0; m < 2; m++) {
        int r0 = (mt_base + m) * 16 + g;
        #pragma unroll
        for (int j = 0; j < 4; j++) {
            int col = (nt_base + j) * 8 + tt * 2;
            *(__half2*)(h16 + (size_t)r0 * 256 + col) =
                __floats2half2_rn(acc[m][j][0], acc[m][j][1]);
            *(__half2*)(h16 + (size_t)(r0 + 8) * 256 + col) =
                __floats2half2_rn(acc[m][j][2], acc[m][j][3]);
        }
    }

    // ---- fused attention logits ----
    __shared__ float satt[2][64 * HL];
    for (int i = t; i < 2 * 64 * HL; i += 256) satt[i / (64 * HL)][i % (64 * HL)] = 0.f;
    __syncthreads();

    int head_local = (HEADS == 4) ? (wn >> 1) : 0;
    int head       = (HEADS == 4) ? (bx * 2 + head_local) : 0;
    float asv[8], adv[8];
    #pragma unroll
    for (int j = 0; j < 4; j++) {
        #pragma unroll
        for (int q = 0; q < 2; q++) {
            int col = (nt_base + j) * 8 + tt * 2 + q;
            int cih = col - head * HID;
            asv[j * 2 + q] = a_src[head * HID + cih];
            adv[j * 2 + q] = a_dst[head * HID + cih];
        }
    }
    #pragma unroll
    for (int m = 0; m < 2; m++) {
        #pragma unroll
        for (int half = 0; half < 2; half++) {
            float ps = 0.f, pd = 0.f;
            #pragma unroll
            for (int j = 0; j < 4; j++) {
                #pragma unroll
                for (int q = 0; q < 2; q++) {
                    float av = acc[m][j][half * 2 + q];
                    ps = fmaf(av, asv[j * 2 + q], ps);
                    pd = fmaf(av, adv[j * 2 + q], pd);
                }
            }
            ps += __shfl_xor_sync(0xFFFFFFFFu, ps, 1);
            ps += __shfl_xor_sync(0xFFFFFFFFu, ps, 2);
            pd += __shfl_xor_sync(0xFFFFFFFFu, pd, 1);
            pd += __shfl_xor_sync(0xFFFFFFFFu, pd, 2);
            if (tt == 0) {
                int rl = (wm * 2 + m) * 16 + half * 8 + g;
                atomicAdd(&satt[0][rl * HL + head_local], ps);
                atomicAdd(&satt[1][rl * HL + head_local], pd);
            }
        }
    }
    __syncthreads();
    for (int i = t; i < 64 * HL; i += 256) {
        int rl = i / HL, hl = i % HL;
        int rg = blockIdx.y * 64 + rl;
        if (rg < n) {
            if (HEADS == 4) {
                int hh = bx * 2 + hl;
                als[(size_t)rg * 4 + hh] = satt[0][i];
                ald[(size_t)rg * 4 + hh] = satt[1][i];
            } else {
                als[(size_t)bx * NNODES + rg] = satt[0][i];
                ald[(size_t)bx * NNODES + rg] = satt[1][i];
            }
        }
    }
}

// ---------------- CSR build (vectorized; self-loops folded into scan) ----------
__global__ void zero_cnt4_kernel(int n4) {
    int i = blockIdx.x * blockDim.x + threadIdx.x;
    if (i < n4) ((int4*)g_cnt)[i] = make_int4(0, 0, 0, 0);
}
__global__ void hist4_kernel(const int* __restrict__ ei, int E4) {
    int i = blockIdx.x * blockDim.x + threadIdx.x;
    if (i >= E4) return;
    int4 d = ((const int4*)ei)[i];
    atomicAdd(&g_cnt[d.x], 1);
    atomicAdd(&g_cnt[d.y], 1);
    atomicAdd(&g_cnt[d.z], 1);
    atomicAdd(&g_cnt[d.w], 1);
}
__global__ void scan1_kernel(int n) {
    __shared__ int sh[1024];
    int t = threadIdx.x;
    int i = blockIdx.x * 1024 + t;
    int v = (i < n) ? (g_cnt[i] + 1) : 0;      // +1 self loop
    sh[t] = v;
    __syncthreads();
    #pragma unroll
    for (int d = 1; d < 1024; d <<= 1) {
        int u = (t >= d) ? sh[t - d] : 0;
        __syncthreads();
        sh[t] += u;
        __syncthreads();
    }
    if (i < n) g_off[i + 1] = sh[t];
    if (t == 1023) g_part[blockIdx.x] = sh[1023];
}
__global__ void scan2_kernel(int nb) {
    __shared__ int sh[64];
    int t = threadIdx.x;
    int v = (t < nb) ? g_part[t] : 0;
    sh[t] = v;
    __syncthreads();
    #pragma unroll
    for (int d = 1; d < 64; d <<= 1) {
        int u = (t >= d) ? sh[t - d] : 0;
        __syncthreads();
        sh[t] += u;
        __syncthreads();
    }
    g_pbase[t] = sh[t] - v;
}
__global__ void scan3_kernel(int n) {
    int i = blockIdx.x * blockDim.x + threadIdx.x;
    if (i >= n) return;
    int base = g_pbase[i >> 10];
    int incl = g_off[i + 1] + base;
    g_off[i + 1] = incl;
    int excl = incl - (g_cnt[i] + 1);
    g_csr[excl] = i;              // self loop occupies first slot
    g_cur[i] = excl + 1;
    if (i == 0) g_off[0] = 0;
}
__global__ void scatter4_kernel(const int* __restrict__ ei, int E, int E4) {
    int i = blockIdx.x * blockDim.x + threadIdx.x;
    if (i >= E4) return;
    int4 s = ((const int4*)ei)[i];
    int4 d = ((const int4*)(ei + E))[i];
    g_csr[atomicAdd(&g_cur[d.x], 1)] = s.x;
    g_csr[atomicAdd(&g_cur[d.y], 1)] = s.y;
    g_csr[atomicAdd(&g_cur[d.z], 1)] = s.z;
    g_csr[atomicAdd(&g_cur[d.w], 1)] = s.w;
}

// ---------------- warp-per-node softmax aggregation ----------------
// OT = float (final output) or __half (layer-2 activation)
template <int HEADS, typename OT>
__global__ void __launch_bounds__(256)
agg_kernel(const __half* __restrict__ h16,
           const float* __restrict__ als,
           const float* __restrict__ ald,
           const float* __restrict__ bias,
           OT* __restrict__ out, int n, int do_elu) {
    int warp = threadIdx.x >> 5, lane = threadIdx.x & 31;
    int node = blockIdx.x * 8 + warp;
    if (node >= n) return;
    int start = g_off[node], deg = g_off[node + 1] - start;

    __shared__ int   ssrc[8][32];
    __shared__ float swt[8][32 * HEADS];

    float aldn[HEADS];
    if (HEADS == 4) {
        #pragma unroll
        for (int hh = 0; hh < 4; hh++) aldn[hh] = ald[(size_t)node * 4 + hh];
    } else {
        aldn[0] = ald[node] + ald[NNODES + node];
    }

    const int myh = (HEADS == 1) ? 0 : (lane >> 3);
    float acc[8];
    #pragma unroll
    for (int q = 0; q < 8; q++) acc[q] = 0.f;
    float dloc[HEADS];
    #pragma unroll
    for (int hh = 0; hh < HEADS; hh++) dloc[hh] = 0.f;

    for (int base = 0; base < deg; base += 32) {
        int cnt = min(32, deg - base);
        if (lane < cnt) {
            int s = g_csr[start + base + lane];
            ssrc[warp][lane] = s;
            if (HEADS == 4) {
                float4 av = *(const float4*)(als + (size_t)s * 4);
                float ev[4] = {av.x + aldn[0], av.y + aldn[1], av.z + aldn[2], av.w + aldn[3]};
                #pragma unroll
                for (int hh = 0; hh < 4; hh++) {
                    float e = ev[hh];
                    e = (e > 0.f) ? e : 0.2f * e;
                    float w = __expf(e);
                    swt[warp][lane * 4 + hh] = w;
                    dloc[hh] += w;
                }
            } else {
                float e = als[s] + als[NNODES + s] + aldn[0];
                e = (e > 0.f) ? e : 0.2f * e;
                float w = __expf(e);
                swt[warp][lane] = w;
                dloc[0] += w;
            }
        }
        __syncwarp();
        int j = 0;
        for (; j + 4 <= cnt; j += 4) {
            int s0 = ssrc[warp][j], s1 = ssrc[warp][j + 1];
            int s2 = ssrc[warp][j + 2], s3 = ssrc[warp][j + 3];
            float w0 = swt[warp][(j + 0) * HEADS + myh];
            float w1 = swt[warp][(j + 1) * HEADS + myh];
            float w2 = swt[warp][(j + 2) * HEADS + myh];
            float w3 = swt[warp][(j + 3) * HEADS + myh];
            uint4 v0 = *(const uint4*)(h16 + (size_t)s0 * 256 + lane * 8);
            uint4 v1 = *(const uint4*)(h16 + (size_t)s1 * 256 + lane * 8);
            uint4 v2 = *(const uint4*)(h16 + (size_t)s2 * 256 + lane * 8);
            uint4 v3 = *(const uint4*)(h16 + (size_t)s3 * 256 + lane * 8);
            const __half2* p0 = (const __half2*)&v0;
            const __half2* p1 = (const __half2*)&v1;
            const __half2* p2 = (const __half2*)&v2;
            const __half2* p3 = (const __half2*)&v3;
            #pragma unroll
            for (int q = 0; q < 4; q++) {
                float2 f0 = __half22float2(p0[q]);
                float2 f1 = __half22float2(p1[q]);
                float2 f2 = __half22float2(p2[q]);
                float2 f3 = __half22float2(p3[q]);
                acc[q * 2 + 0] = fmaf(f0.x, w0, acc[q * 2 + 0]);
                acc[q * 2 + 1] = fmaf(f0.y, w0, acc[q * 2 + 1]);
                acc[q * 2 + 0] = fmaf(f1.x, w1, acc[q * 2 + 0]);
                acc[q * 2 + 1] = fmaf(f1.y, w1, acc[q * 2 + 1]);
                acc[q * 2 + 0] = fmaf(f2.x, w2, acc[q * 2 + 0]);
                acc[q * 2 + 1] = fmaf(f2.y, w2, acc[q * 2 + 1]);
                acc[q * 2 + 0] = fmaf(f3.x, w3, acc[q * 2 + 0]);
                acc[q * 2 + 1] = fmaf(f3.y, w3, acc[q * 2 + 1]);
            }
        }
        for (; j < cnt; j++) {
            int s0 = ssrc[warp][j];
            float w0 = swt[warp][j * HEADS + myh];
            uint4 v0 = *(const uint4*)(h16 + (size_t)s0 * 256 + lane * 8);
            const __half2* p0 = (const __half2*)&v0;
            #pragma unroll
            for (int q = 0; q < 4; q++) {
                float2 f0 = __half22float2(p0[q]);
                acc[q * 2 + 0] = fmaf(f0.x, w0, acc[q * 2 + 0]);
                acc[q * 2 + 1] = fmaf(f0.y, w0, acc[q * 2 + 1]);
            }
        }
        __syncwarp();
    }

    #pragma unroll
    for (int hh = 0; hh < HEADS; hh++)
        #pragma unroll
        for (int o = 16; o; o >>= 1)
            dloc[hh] += __shfl_xor_sync(0xFFFFFFFFu, dloc[hh], o);
    float inv = 1.f / (dloc[myh] + 1e-16f);

    float4 bv0 = *(const float4*)(bias + lane * 8);
    float4 bv1 = *(const float4*)(bias + lane * 8 + 4);
    float o0[8] = { acc[0] * inv + bv0.x, acc[1] * inv + bv0.y,
                    acc[2] * inv + bv0.z, acc[3] * inv + bv0.w,
                    acc[4] * inv + bv1.x, acc[5] * inv + bv1.y,
                    acc[6] * inv + bv1.z, acc[7] * inv + bv1.w };
    if (do_elu) {
        #pragma unroll
        for (int q = 0; q < 8; q++) o0[q] = (o0[q] > 0.f) ? o0[q] : (__expf(o0[q]) - 1.f);
    }
    if (sizeof(OT) == 4) {
        float* op = (float*)out + (size_t)node * 256 + lane * 8;
        *(float4*)(op)     = make_float4(o0[0], o0[1], o0[2], o0[3]);
        *(float4*)(op + 4) = make_float4(o0[4], o0[5], o0[6], o0[7]);
    } else {
        __half* op = (__half*)out + (size_t)node * 256 + lane * 8;
        __half2 hv[4] = { __floats2half2_rn(o0[0], o0[1]), __floats2half2_rn(o0[2], o0[3]),
                          __floats2half2_rn(o0[4], o0[5]), __floats2half2_rn(o0[6], o0[7]) };
        *(uint4*)op = *(uint4*)hv;
    }
}

// ---------------- launch ----------------
extern "C" void kernel_launch(void* const* d_in, const int* in_sizes, int n_in,
                              void* d_out, int out_size) {
    const float* x        = (const float*)d_in[0];
    const int*   ei       = (const int*)  d_in[1];
    const float* W1       = (const float*)d_in[2];
    const float* att_src1 = (const float*)d_in[3];
    const float* att_dst1 = (const float*)d_in[4];
    const float* b1       = (const float*)d_in[5];
    const float* W2       = (const float*)d_in[6];
    const float* att_src2 = (const float*)d_in[7];
    const float* att_dst2 = (const float*)d_in[8];
    const float* b2       = (const float*)d_in[9];
    float* out = (float*)d_out;

    int n  = in_sizes[0] / FDIM;   // 50000
    int E  = in_sizes[1] / 2;      // 800000
    int E4 = E / 4;
    int n4 = (n + 3) / 4;
    int nb = (n + 1023) / 1024;

    float *p_act, *p_als, *p_ald;
    __half* p_h16;
    __nv_bfloat16 *p_b1hi, *p_b1lo, *p_b2hi, *p_b2lo;
    cudaGetSymbolAddress((void**)&p_h16,  g_h16);
    cudaGetSymbolAddress((void**)&p_act,  g_act);
    cudaGetSymbolAddress((void**)&p_als,  g_als);
    cudaGetSymbolAddress((void**)&p_ald,  g_ald);
    cudaGetSymbolAddress((void**)&p_b1hi, g_b1hi);
    cudaGetSymbolAddress((void**)&p_b1lo, g_b1lo);
    cudaGetSymbolAddress((void**)&p_b2hi, g_b2hi);
    cudaGetSymbolAddress((void**)&p_b2lo, g_b2lo);
    __half* p_act16 = (__half*)p_act;

    // one-time side stream + events
    static cudaStream_t s2 = nullptr;
    static cudaEvent_t evFork = nullptr, evJoin = nullptr;
    if (s2 == nullptr) {
        cudaStreamCreateWithFlags(&s2, cudaStreamNonBlocking);
        cudaEventCreateWithFlags(&evFork, cudaEventDisableTiming);
        cudaEventCreateWithFlags(&evJoin, cudaEventDisableTiming);
    }

    int wu = FDIM * FDIM / 2;
    dim3 gg(2, MPAD / 64);

    // main stream: conv1 -> gemm1
    conv_wfrag_kernel<<<(wu + 255) / 256, 256>>>(W1, (uint32_t*)p_b1hi, (uint32_t*)p_b1lo);
    cudaEventRecord(evFork, 0);
    cudaStreamWaitEvent(s2, evFork, 0);

    // side stream: CSR build + conv2 (independent of gemm1)
    conv_wfrag_kernel<<<(wu + 255) / 256, 256, 0, s2>>>(W2, (uint32_t*)p_b2hi, (uint32_t*)p_b2lo);
    zero_cnt4_kernel<<<(n4 + 255) / 256, 256, 0, s2>>>(n4);
    hist4_kernel<<<(E4 + 255) / 256, 256, 0, s2>>>(ei + E, E4);
    scan1_kernel<<<nb, 1024, 0, s2>>>(n);
    scan2_kernel<<<1, 64, 0, s2>>>(nb);
    scan3_kernel<<<(n + 1023) / 1024, 1024, 0, s2>>>(n);
    scatter4_kernel<<<(E4 + 255) / 256, 256, 0, s2>>>(ei, E, E4);
    cudaEventRecord(evJoin, s2);

    // main stream: gemm1 overlaps side stream
    gemm_mma_kernel<HEADS1, float><<<gg, 256>>>(
        x, (const uint2*)p_b1hi, (const uint2*)p_b1lo, p_h16,
        att_src1, att_dst1, p_als, p_ald, n);

    cudaStreamWaitEvent(0, evJoin, 0);   // join before agg1

    // agg1 writes fp16 activations
    agg_kernel<HEADS1, __half><<<(n + 7) / 8, 256>>>(
        p_h16, p_als, p_ald, b1, p_act16, n, 1);

    // gemm2 reads fp16 activations (exact split: fp16 -> bf16 hi+lo)
    gemm_mma_kernel<1, __half><<<gg, 256>>>(
        p_act16, (const uint2*)p_b2hi, (const uint2*)p_b2lo, p_h16,
        att_src2, att_dst2, p_als, p_ald, n);
    agg_kernel<1, float><<<(n + 7) / 8, 256>>>(
        p_h16, p_als, p_ald, b2, out, n, 0);
}

// round 17
// speedup vs baseline: 1.1657x; 1.1657x over previous
#include <cuda_runtime.h>
#include <cuda_bf16.h>
#include <cuda_fp16.h>
#include <cstdint>

#define NNODES 50000
#define FDIM   256
#define HEADS1 4
#define MAXE   900000
#define MPAD   50048

// ---------------- device scratch ----------------
__device__ __align__(16) __half g_h16[(size_t)MPAD * FDIM];
__device__ __align__(16) float g_act[(size_t)NNODES * FDIM];   // reused as __half for layer-2 input
__device__ __align__(16) float g_als[(size_t)NNODES * HEADS1];
__device__ __align__(16) float g_ald[(size_t)NNODES * HEADS1];
__device__ __align__(16) int g_cnt[NNODES];
__device__ int   g_off[NNODES + 1];
__device__ int   g_cur[NNODES];
__device__ int   g_csr[MAXE];
__device__ int   g_part[64];
__device__ int   g_pbase[64];
__device__ __align__(16) __nv_bfloat16 g_b1hi[FDIM * FDIM];
__device__ __align__(16) __nv_bfloat16 g_b1lo[FDIM * FDIM];
__device__ __align__(16) __nv_bfloat16 g_b2hi[FDIM * FDIM];
__device__ __align__(16) __nv_bfloat16 g_b2lo[FDIM * FDIM];

// ---------------- HMMA + split helpers ----------------
__device__ __forceinline__ void mma16816(float* c, const uint4& a, const uint2& b) {
    asm volatile(
        "mma.sync.aligned.m16n8k16.row.col.f32.bf16.bf16.f32 "
        "{%0,%1,%2,%3}, {%4,%5,%6,%7}, {%8,%9}, {%0,%1,%2,%3};"
        : "+f"(c[0]), "+f"(c[1]), "+f"(c[2]), "+f"(c[3])
        : "r"(a.x), "r"(a.y), "r"(a.z), "r"(a.w), "r"(b.x), "r"(b.y));
}

__device__ __forceinline__ void split2(float2 v, uint32_t& hi, uint32_t& lo) {
    uint32_t ux = __float_as_uint(v.x), uy = __float_as_uint(v.y);
    hi = __byte_perm(ux, uy, 0x7632);
    float lx = v.x - __uint_as_float(ux & 0xFFFF0000u);
    float ly = v.y - __uint_as_float(uy & 0xFFFF0000u);
    asm("cvt.rn.bf16x2.f32 %0, %1, %2;" : "=r"(lo) : "f"(ly), "f"(lx));
}

// A-tile loaders: fp32 or fp16 input, both return float2
__device__ __forceinline__ float2 lda_t(const float* __restrict__ A, int row, int k, int n) {
    return (row < n) ? *(const float2*)(A + (size_t)row * 256 + k) : make_float2(0.f, 0.f);
}
__device__ __forceinline__ float2 lda_t(const __half* __restrict__ A, int row, int k, int n) {
    return (row < n) ? __half22float2(*(const __half2*)(A + (size_t)row * 256 + k))
                     : make_float2(0.f, 0.f);
}

// ---------------- W fragment conversion ----------------
__global__ void conv_wfrag_kernel(const float* __restrict__ W,
                                  uint32_t* __restrict__ hi, uint32_t* __restrict__ lo) {
    int u = blockIdx.x * blockDim.x + threadIdx.x;
    if (u >= FDIM * FDIM / 2) return;
    int r    = u & 1;
    int lane = (u >> 1) & 31;
    int blk  = u >> 6;
    int kstep = blk & 15;
    int ntile = blk >> 4;
    int g = lane >> 2, tig = lane & 3;
    int nn = ntile * 8 + g;
    int k  = kstep * 16 + r * 8 + tig * 2;
    float2 v = make_float2(W[(size_t)k * 256 + nn], W[(size_t)(k + 1) * 256 + nn]);
    uint32_t h, l;
    split2(v, h, l);
    hi[u] = h; lo[u] = l;
}

// ---------------- HMMA GEMM (64x128 block, 2m x 4n warps) + fused epilogue -------
template <int HEADS, typename AT>
__global__ void __launch_bounds__(256)
gemm_mma_kernel(const AT* __restrict__ A,
                const uint2* __restrict__ b_hi, const uint2* __restrict__ b_lo,
                __half* __restrict__ h16,
                const float* __restrict__ a_src, const float* __restrict__ a_dst,
                float* __restrict__ als, float* __restrict__ ald, int n) {
    constexpr int HID = 256 / HEADS;
    constexpr int HL  = (HEADS == 4) ? 2 : 1;
    int t = threadIdx.x, lane = t & 31, wid = t >> 5;
    int wm = wid & 1, wn = wid >> 1;
    int bx = blockIdx.x;
    int mt_base = blockIdx.y * 4 + wm * 2;
    int nt_base = bx * 16 + wn * 4;
    int g = lane >> 2, tig = lane & 3, tt = lane & 3;

    float acc[2][4][4];
    #pragma unroll
    for (int m = 0; m < 2; m++)
        #pragma unroll
        for (int j = 0; j < 4; j++)
            #pragma unroll
            for (int q = 0; q < 4; q++) acc[m][j][q] = 0.f;

    #pragma unroll 2
    for (int ks = 0; ks < 16; ks++) {
        int kk = ks * 16 + tig * 2;
        uint4 ah[2], al[2];
        #pragma unroll
        for (int m = 0; m < 2; m++) {
            int row0 = (mt_base + m) * 16 + g;
            float2 v00 = lda_t(A, row0,     kk,     n);
            float2 v10 = lda_t(A, row0 + 8, kk,     n);
            float2 v01 = lda_t(A, row0,     kk + 8, n);
            float2 v11 = lda_t(A, row0 + 8, kk + 8, n);
            split2(v00, ah[m].x, al[m].x);
            split2(v10, ah[m].y, al[m].y);
            split2(v01, ah[m].z, al[m].z);
            split2(v11, ah[m].w, al[m].w);
        }
        uint2 bh[4], bl[4];
        #pragma unroll
        for (int j = 0; j < 4; j++) {
            int idx = ((nt_base + j) * 16 + ks) * 32 + lane;
            bh[j] = b_hi[idx];
            bl[j] = b_lo[idx];
        }
        #pragma unroll
        for (int m = 0; m < 2; m++)
            #pragma unroll
            for (int j = 0; j < 4; j++) {
                mma16816(acc[m][j], ah[m], bh[j]);
                mma16816(acc[m][j], ah[m], bl[j]);
                mma16816(acc[m][j], al[m], bh[j]);
            }
    }

    // ---- store fp16 features ----
    #pragma unroll
    for (int m = 0; m < 2; m++) {
        int r0 = (mt_base + m) * 16 + g;
        #pragma unroll
        for (int j = 0; j < 4; j++) {
            int col = (nt_base + j) * 8 + tt * 2;
            *(__half2*)(h16 + (size_t)r0 * 256 + col) =
                __floats2half2_rn(acc[m][j][0], acc[m][j][1]);
            *(__half2*)(h16 + (size_t)(r0 + 8) * 256 + col) =
                __floats2half2_rn(acc[m][j][2], acc[m][j][3]);
        }
    }

    // ---- fused attention logits ----
    __shared__ float satt[2][64 * HL];
    for (int i = t; i < 2 * 64 * HL; i += 256) satt[i / (64 * HL)][i % (64 * HL)] = 0.f;
    __syncthreads();

    int head_local = (HEADS == 4) ? (wn >> 1) : 0;
    int head       = (HEADS == 4) ? (bx * 2 + head_local) : 0;
    float asv[8], adv[8];
    #pragma unroll
    for (int j = 0; j < 4; j++) {
        #pragma unroll
        for (int q = 0; q < 2; q++) {
            int col = (nt_base + j) * 8 + tt * 2 + q;
            int cih = col - head * HID;
            asv[j * 2 + q] = a_src[head * HID + cih];
            adv[j * 2 + q] = a_dst[head * HID + cih];
        }
    }
    #pragma unroll
    for (int m = 0; m < 2; m++) {
        #pragma unroll
        for (int half = 0; half < 2; half++) {
            float ps = 0.f, pd = 0.f;
            #pragma unroll
            for (int j = 0; j < 4; j++) {
                #pragma unroll
                for (int q = 0; q < 2; q++) {
                    float av = acc[m][j][half * 2 + q];
                    ps = fmaf(av, asv[j * 2 + q], ps);
                    pd = fmaf(av, adv[j * 2 + q], pd);
                }
            }
            ps += __shfl_xor_sync(0xFFFFFFFFu, ps, 1);
            ps += __shfl_xor_sync(0xFFFFFFFFu, ps, 2);
            pd += __shfl_xor_sync(0xFFFFFFFFu, pd, 1);
            pd += __shfl_xor_sync(0xFFFFFFFFu, pd, 2);
            if (tt == 0) {
                int rl = (wm * 2 + m) * 16 + half * 8 + g;
                atomicAdd(&satt[0][rl * HL + head_local], ps);
                atomicAdd(&satt[1][rl * HL + head_local], pd);
            }
        }
    }
    __syncthreads();
    for (int i = t; i < 64 * HL; i += 256) {
        int rl = i / HL, hl = i % HL;
        int rg = blockIdx.y * 64 + rl;
        if (rg < n) {
            if (HEADS == 4) {
                int hh = bx * 2 + hl;
                als[(size_t)rg * 4 + hh] = satt[0][i];
                ald[(size_t)rg * 4 + hh] = satt[1][i];
            } else {
                als[(size_t)bx * NNODES + rg] = satt[0][i];
                ald[(size_t)bx * NNODES + rg] = satt[1][i];
            }
        }
    }
}

// ---------------- CSR build (vectorized; self-loops folded into scan) ----------
__global__ void zero_cnt4_kernel(int n4) {
    int i = blockIdx.x * blockDim.x + threadIdx.x;
    if (i < n4) ((int4*)g_cnt)[i] = make_int4(0, 0, 0, 0);
}
__global__ void hist4_kernel(const int* __restrict__ ei, int E4) {
    int i = blockIdx.x * blockDim.x + threadIdx.x;
    if (i >= E4) return;
    int4 d = ((const int4*)ei)[i];
    atomicAdd(&g_cnt[d.x], 1);
    atomicAdd(&g_cnt[d.y], 1);
    atomicAdd(&g_cnt[d.z], 1);
    atomicAdd(&g_cnt[d.w], 1);
}
__global__ void scan1_kernel(int n) {
    __shared__ int sh[1024];
    int t = threadIdx.x;
    int i = blockIdx.x * 1024 + t;
    int v = (i < n) ? (g_cnt[i] + 1) : 0;      // +1 self loop
    sh[t] = v;
    __syncthreads();
    #pragma unroll
    for (int d = 1; d < 1024; d <<= 1) {
        int u = (t >= d) ? sh[t - d] : 0;
        __syncthreads();
        sh[t] += u;
        __syncthreads();
    }
    if (i < n) g_off[i + 1] = sh[t];
    if (t == 1023) g_part[blockIdx.x] = sh[1023];
}
__global__ void scan2_kernel(int nb) {
    __shared__ int sh[64];
    int t = threadIdx.x;
    int v = (t < nb) ? g_part[t] : 0;
    sh[t] = v;
    __syncthreads();
    #pragma unroll
    for (int d = 1; d < 64; d <<= 1) {
        int u = (t >= d) ? sh[t - d] : 0;
        __syncthreads();
        sh[t] += u;
        __syncthreads();
    }
    g_pbase[t] = sh[t] - v;
}
__global__ void scan3_kernel(int n) {
    int i = blockIdx.x * blockDim.x + threadIdx.x;
    if (i >= n) return;
    int base = g_pbase[i >> 10];
    int incl = g_off[i + 1] + base;
    g_off[i + 1] = incl;
    int excl = incl - (g_cnt[i] + 1);
    g_csr[excl] = i;              // self loop occupies first slot
    g_cur[i] = excl + 1;
    if (i == 0) g_off[0] = 0;
}
__global__ void scatter4_kernel(const int* __restrict__ ei, int E, int E4) {
    int i = blockIdx.x * blockDim.x + threadIdx.x;
    if (i >= E4) return;
    int4 s = ((const int4*)ei)[i];
    int4 d = ((const int4*)(ei + E))[i];
    g_csr[atomicAdd(&g_cur[d.x], 1)] = s.x;
    g_csr[atomicAdd(&g_cur[d.y], 1)] = s.y;
    g_csr[atomicAdd(&g_cur[d.z], 1)] = s.z;
    g_csr[atomicAdd(&g_cur[d.w], 1)] = s.w;
}

// ---------------- warp-per-node softmax aggregation ----------------
// OT = float (final output) or __half (layer-2 activation)
template <int HEADS, typename OT>
__global__ void __launch_bounds__(256)
agg_kernel(const __half* __restrict__ h16,
           const float* __restrict__ als,
           const float* __restrict__ ald,
           const float* __restrict__ bias,
           OT* __restrict__ out, int n, int do_elu) {
    int warp = threadIdx.x >> 5, lane = threadIdx.x & 31;
    int node = blockIdx.x * 8 + warp;
    if (node >= n) return;
    int start = g_off[node], deg = g_off[node + 1] - start;

    __shared__ int   ssrc[8][32];
    __shared__ float swt[8][32 * HEADS];

    float aldn[HEADS];
    if (HEADS == 4) {
        #pragma unroll
        for (int hh = 0; hh < 4; hh++) aldn[hh] = ald[(size_t)node * 4 + hh];
    } else {
        aldn[0] = ald[node] + ald[NNODES + node];
    }

    const int myh = (HEADS == 1) ? 0 : (lane >> 3);
    float acc[8];
    #pragma unroll
    for (int q = 0; q < 8; q++) acc[q] = 0.f;
    float dloc[HEADS];
    #pragma unroll
    for (int hh = 0; hh < HEADS; hh++) dloc[hh] = 0.f;

    for (int base = 0; base < deg; base += 32) {
        int cnt = min(32, deg - base);
        if (lane < cnt) {
            int s = g_csr[start + base + lane];
            ssrc[warp][lane] = s;
            if (HEADS == 4) {
                float4 av = *(const float4*)(als + (size_t)s * 4);
                float ev[4] = {av.x + aldn[0], av.y + aldn[1], av.z + aldn[2], av.w + aldn[3]};
                #pragma unroll
                for (int hh = 0; hh < 4; hh++) {
                    float e = ev[hh];
                    e = (e > 0.f) ? e : 0.2f * e;
                    float w = __expf(e);
                    swt[warp][lane * 4 + hh] = w;
                    dloc[hh] += w;
                }
            } else {
                float e = als[s] + als[NNODES + s] + aldn[0];
                e = (e > 0.f) ? e : 0.2f * e;
                float w = __expf(e);
                swt[warp][lane] = w;
                dloc[0] += w;
            }
        }
        __syncwarp();
        int j = 0;
        for (; j + 2 <= cnt; j += 2) {
            int s0 = ssrc[warp][j], s1 = ssrc[warp][j + 1];
            float w0 = swt[warp][j * HEADS + myh];
            float w1 = swt[warp][(j + 1) * HEADS + myh];
            uint4 v0 = *(const uint4*)(h16 + (size_t)s0 * 256 + lane * 8);
            uint4 v1 = *(const uint4*)(h16 + (size_t)s1 * 256 + lane * 8);
            const __half2* p0 = (const __half2*)&v0;
            const __half2* p1 = (const __half2*)&v1;
            #pragma unroll
            for (int q = 0; q < 4; q++) {
                float2 f0 = __half22float2(p0[q]);
                float2 f1 = __half22float2(p1[q]);
                acc[q * 2 + 0] = fmaf(f0.x, w0, acc[q * 2 + 0]);
                acc[q * 2 + 1] = fmaf(f0.y, w0, acc[q * 2 + 1]);
                acc[q * 2 + 0] = fmaf(f1.x, w1, acc[q * 2 + 0]);
                acc[q * 2 + 1] = fmaf(f1.y, w1, acc[q * 2 + 1]);
            }
        }
        if (j < cnt) {
            int s0 = ssrc[warp][j];
            float w0 = swt[warp][j * HEADS + myh];
            uint4 v0 = *(const uint4*)(h16 + (size_t)s0 * 256 + lane * 8);
            const __half2* p0 = (const __half2*)&v0;
            #pragma unroll
            for (int q = 0; q < 4; q++) {
                float2 f0 = __half22float2(p0[q]);
                acc[q * 2 + 0] = fmaf(f0.x, w0, acc[q * 2 + 0]);
                acc[q * 2 + 1] = fmaf(f0.y, w0, acc[q * 2 + 1]);
            }
        }
        __syncwarp();
    }

    #pragma unroll
    for (int hh = 0; hh < HEADS; hh++)
        #pragma unroll
        for (int o = 16; o; o >>= 1)
            dloc[hh] += __shfl_xor_sync(0xFFFFFFFFu, dloc[hh], o);
    float inv = 1.f / (dloc[myh] + 1e-16f);

    float4 bv0 = *(const float4*)(bias + lane * 8);
    float4 bv1 = *(const float4*)(bias + lane * 8 + 4);
    float o0[8] = { acc[0] * inv + bv0.x, acc[1] * inv + bv0.y,
                    acc[2] * inv + bv0.z, acc[3] * inv + bv0.w,
                    acc[4] * inv + bv1.x, acc[5] * inv + bv1.y,
                    acc[6] * inv + bv1.z, acc[7] * inv + bv1.w };
    if (do_elu) {
        #pragma unroll
        for (int q = 0; q < 8; q++) o0[q] = (o0[q] > 0.f) ? o0[q] : (__expf(o0[q]) - 1.f);
    }
    if (sizeof(OT) == 4) {
        float* op = (float*)out + (size_t)node * 256 + lane * 8;
        *(float4*)(op)     = make_float4(o0[0], o0[1], o0[2], o0[3]);
        *(float4*)(op + 4) = make_float4(o0[4], o0[5], o0[6], o0[7]);
    } else {
        __half* op = (__half*)out + (size_t)node * 256 + lane * 8;
        __half2 hv[4] = { __floats2half2_rn(o0[0], o0[1]), __floats2half2_rn(o0[2], o0[3]),
                          __floats2half2_rn(o0[4], o0[5]), __floats2half2_rn(o0[6], o0[7]) };
        *(uint4*)op = *(uint4*)hv;
    }
}

// ---------------- launch ----------------
extern "C" void kernel_launch(void* const* d_in, const int* in_sizes, int n_in,
                              void* d_out, int out_size) {
    const float* x        = (const float*)d_in[0];
    const int*   ei       = (const int*)  d_in[1];
    const float* W1       = (const float*)d_in[2];
    const float* att_src1 = (const float*)d_in[3];
    const float* att_dst1 = (const float*)d_in[4];
    const float* b1       = (const float*)d_in[5];
    const float* W2       = (const float*)d_in[6];
    const float* att_src2 = (const float*)d_in[7];
    const float* att_dst2 = (const float*)d_in[8];
    const float* b2       = (const float*)d_in[9];
    float* out = (float*)d_out;

    int n  = in_sizes[0] / FDIM;   // 50000
    int E  = in_sizes[1] / 2;      // 800000
    int E4 = E / 4;
    int n4 = (n + 3) / 4;
    int nb = (n + 1023) / 1024;

    float *p_act, *p_als, *p_ald;
    __half* p_h16;
    __nv_bfloat16 *p_b1hi, *p_b1lo, *p_b2hi, *p_b2lo;
    cudaGetSymbolAddress((void**)&p_h16,  g_h16);
    cudaGetSymbolAddress((void**)&p_act,  g_act);
    cudaGetSymbolAddress((void**)&p_als,  g_als);
    cudaGetSymbolAddress((void**)&p_ald,  g_ald);
    cudaGetSymbolAddress((void**)&p_b1hi, g_b1hi);
    cudaGetSymbolAddress((void**)&p_b1lo, g_b1lo);
    cudaGetSymbolAddress((void**)&p_b2hi, g_b2hi);
    cudaGetSymbolAddress((void**)&p_b2lo, g_b2lo);
    __half* p_act16 = (__half*)p_act;     // act reused as fp16 buffer (half the bytes)

    // one-time side stream + events
    static cudaStream_t s2 = nullptr;
    static cudaEvent_t evFork = nullptr, evJoin = nullptr;
    if (s2 == nullptr) {
        cudaStreamCreateWithFlags(&s2, cudaStreamNonBlocking);
        cudaEventCreateWithFlags(&evFork, cudaEventDisableTiming);
        cudaEventCreateWithFlags(&evJoin, cudaEventDisableTiming);
    }

    int wu = FDIM * FDIM / 2;
    dim3 gg(2, MPAD / 64);

    // main stream: conv1 -> gemm1
    conv_wfrag_kernel<<<(wu + 255) / 256, 256>>>(W1, (uint32_t*)p_b1hi, (uint32_t*)p_b1lo);
    cudaEventRecord(evFork, 0);
    cudaStreamWaitEvent(s2, evFork, 0);

    // side stream: CSR build + conv2 (independent of gemm1)
    conv_wfrag_kernel<<<(wu + 255) / 256, 256, 0, s2>>>(W2, (uint32_t*)p_b2hi, (uint32_t*)p_b2lo);
    zero_cnt4_kernel<<<(n4 + 255) / 256, 256, 0, s2>>>(n4);
    hist4_kernel<<<(E4 + 255) / 256, 256, 0, s2>>>(ei + E, E4);
    scan1_kernel<<<nb, 1024, 0, s2>>>(n);
    scan2_kernel<<<1, 64, 0, s2>>>(nb);
    scan3_kernel<<<(n + 1023) / 1024, 1024, 0, s2>>>(n);
    scatter4_kernel<<<(E4 + 255) / 256, 256, 0, s2>>>(ei, E, E4);
    cudaEventRecord(evJoin, s2);

    // main stream: gemm1 overlaps side stream
    gemm_mma_kernel<HEADS1, float><<<gg, 256>>>(
        x, (const uint2*)p_b1hi, (const uint2*)p_b1lo, p_h16,
        att_src1, att_dst1, p_als, p_ald, n);

    cudaStreamWaitEvent(0, evJoin, 0);   // join before agg1

    // agg1 writes fp16 activations
    agg_kernel<HEADS1, __half><<<(n + 7) / 8, 256>>>(
        p_h16, p_als, p_ald, b1, p_act16, n, 1);

    // gemm2 reads fp16 activations (exact split: fp16 -> bf16 hi+lo)
    gemm_mma_kernel<1, __half><<<gg, 256>>>(
        p_act16, (const uint2*)p_b2hi, (const uint2*)p_b2lo, p_h16,
        att_src2, att_dst2, p_als, p_ald, n);
    agg_kernel<1, float><<<(n + 7) / 8, 256>>>(
        p_h16, p_als, p_ald, b2, out, n, 0);
}